// round 9
// baseline (speedup 1.0000x reference)
#include <cuda_runtime.h>

#define D_MODEL 1024
#define SEQ     2048
#define BATCH   2
#define NH      16
#define DH      64
#define MROWS   (BATCH * SEQ)   /* 4096 */

// ---------------- scratch (static device arrays; no runtime allocation) -----
__device__ float g_W[4][D_MODEL * D_MODEL];   // q,k,v,o dense weights (out,in)
__device__ float g_Qp[MROWS * D_MODEL];
__device__ float g_Kp[MROWS * D_MODEL];
__device__ float g_Vp[MROWS * D_MODEL];
__device__ float g_AO[MROWS * D_MODEL];       // attention output, [b,s,h*64+d]

// ---------------- TT cores -> dense W ---------------------------------------
// W[(i1*32+i2)][(j1*32+j2)] = sum_r g0[0,i1,j1,r] * g1[r,i2,j2,0]
__global__ void build_w_kernel(const float* __restrict__ g0,
                               const float* __restrict__ g1,
                               int wsel)
{
    int idx = blockIdx.x * blockDim.x + threadIdx.x;   // over 1024*1024
    int n = idx >> 10;
    int k = idx & 1023;
    int i1 = n >> 5, i2 = n & 31;
    int j1 = k >> 5, j2 = k & 31;
    const float* a = &g0[(i1 * 32 + j1) * 8];
    float s = 0.f;
#pragma unroll
    for (int r = 0; r < 8; r++)
        s += a[r] * g1[(r * 32 + i2) * 32 + j2];
    g_W[wsel][idx] = s;
}

// ---------------- GEMM: Y[M,1024] = X[M,1024] @ W^T + bias ------------------
// BM=BN=128, BK=8, 256 threads, 8x8 per thread (split 64+64 tiles for
// conflict-light float4 fragment loads).
#define BM 128
#define BN 128
#define BK 8

__global__ __launch_bounds__(256)
void gemm_kernel(const float* __restrict__ Xext, int xsel, int wsel,
                 const float* __restrict__ bias,
                 float* __restrict__ Yext, int ysel)
{
    const float* X = (xsel == 3) ? g_AO : Xext;
    const float* W = g_W[wsel];
    float* Y = (ysel == 0) ? g_Qp : (ysel == 1) ? g_Kp
             : (ysel == 2) ? g_Vp : Yext;

    __shared__ float Xs[BK][BM];   // transposed: Xs[k][m]
    __shared__ float Ws[BK][BN];   // transposed: Ws[k][n]

    int tid = threadIdx.x;
    int tx = tid & 15, ty = tid >> 4;
    int bm = blockIdx.y * BM;
    int bn = blockIdx.x * BN;

    int lr = tid >> 1;            // 0..127 : row within tile
    int lk = (tid & 1) << 2;      // 0 or 4 : k offset (float4)

    const float* Xp = X + (size_t)(bm + lr) * D_MODEL + lk;
    const float* Wp = W + (size_t)(bn + lr) * D_MODEL + lk;

    float acc[8][8];
#pragma unroll
    for (int i = 0; i < 8; i++)
#pragma unroll
        for (int j = 0; j < 8; j++) acc[i][j] = 0.f;

    for (int k0 = 0; k0 < D_MODEL; k0 += BK) {
        float4 xv = *(const float4*)(Xp + k0);
        float4 wv = *(const float4*)(Wp + k0);
        Xs[lk + 0][lr] = xv.x; Xs[lk + 1][lr] = xv.y;
        Xs[lk + 2][lr] = xv.z; Xs[lk + 3][lr] = xv.w;
        Ws[lk + 0][lr] = wv.x; Ws[lk + 1][lr] = wv.y;
        Ws[lk + 2][lr] = wv.z; Ws[lk + 3][lr] = wv.w;
        __syncthreads();
#pragma unroll
        for (int kk = 0; kk < BK; kk++) {
            float a[8], b[8];
            *(float4*)&a[0] = *(const float4*)&Xs[kk][4 * ty];
            *(float4*)&a[4] = *(const float4*)&Xs[kk][64 + 4 * ty];
            *(float4*)&b[0] = *(const float4*)&Ws[kk][4 * tx];
            *(float4*)&b[4] = *(const float4*)&Ws[kk][64 + 4 * tx];
#pragma unroll
            for (int i = 0; i < 8; i++)
#pragma unroll
                for (int j = 0; j < 8; j++)
                    acc[i][j] += a[i] * b[j];
        }
        __syncthreads();
    }

#pragma unroll
    for (int ih = 0; ih < 2; ih++) {
#pragma unroll
        for (int i = 0; i < 4; i++) {
            int row = bm + ih * 64 + 4 * ty + i;
#pragma unroll
            for (int jh = 0; jh < 2; jh++) {
                int col = bn + jh * 64 + 4 * tx;
                float4 r;
                r.x = acc[ih * 4 + i][jh * 4 + 0] + bias[col + 0];
                r.y = acc[ih * 4 + i][jh * 4 + 1] + bias[col + 1];
                r.z = acc[ih * 4 + i][jh * 4 + 2] + bias[col + 2];
                r.w = acc[ih * 4 + i][jh * 4 + 3] + bias[col + 3];
                *(float4*)(Y + (size_t)row * D_MODEL + col) = r;
            }
        }
    }
}

// ---------------- Flash attention -------------------------------------------
// Per block: one (b, h, 64-query tile). 256 threads as 16x16; each thread
// owns a 4(q) x 4(k/d) micro-tile. K smem is float4-group XOR-swizzled
// (slot = (g + kj + kj/4) & 15) so the k-strided fragment reads are 2-way max.
// P overwrites the K buffer between the two sub-GEMM phases -> exactly 48 KB.
__global__ __launch_bounds__(256)
void flash_kernel()
{
    __shared__ float Qs[64 * 64];
    __shared__ float KPs[64 * 64];   // union: swizzled K tile, then P tile
    __shared__ float Vs[64 * 64];

    int tid = threadIdx.x;
    int tx = tid & 15, ty = tid >> 4;
    int b = blockIdx.z, h = blockIdx.y;
    int qb = blockIdx.x * 64;

    const float* Qg = g_Qp + (size_t)b * SEQ * D_MODEL + h * DH;
    const float* Kg = g_Kp + (size_t)b * SEQ * D_MODEL + h * DH;
    const float* Vg = g_Vp + (size_t)b * SEQ * D_MODEL + h * DH;

    int f4 = tid & 15;    // float4 group along d
    int r0 = tid >> 4;    // base row

    // load Q tile, fold 1/sqrt(64) scale
#pragma unroll
    for (int it = 0; it < 4; it++) {
        int r = r0 + 16 * it;
        float4 v = *(const float4*)(Qg + (size_t)(qb + r) * D_MODEL + f4 * 4);
        v.x *= 0.125f; v.y *= 0.125f; v.z *= 0.125f; v.w *= 0.125f;
        *(float4*)&Qs[r * 64 + f4 * 4] = v;
    }

    float m[4], l[4], o[4][4];
#pragma unroll
    for (int i = 0; i < 4; i++) {
        m[i] = -1e30f; l[i] = 0.f;
#pragma unroll
        for (int j = 0; j < 4; j++) o[i][j] = 0.f;
    }

    for (int kt = 0; kt < SEQ; kt += 64) {
        __syncthreads();   // previous PV / P reads done before overwrite
#pragma unroll
        for (int it = 0; it < 4; it++) {
            int r = r0 + 16 * it;
            float4 kv = *(const float4*)(Kg + (size_t)(kt + r) * D_MODEL + f4 * 4);
            int slot = (f4 + r + (r >> 2)) & 15;
            *(float4*)&KPs[r * 64 + slot * 4] = kv;
            float4 vv = *(const float4*)(Vg + (size_t)(kt + r) * D_MODEL + f4 * 4);
            *(float4*)&Vs[r * 64 + f4 * 4] = vv;
        }
        __syncthreads();

        // ---- S = Q K^T (Q pre-scaled) ----
        float s[4][4];
#pragma unroll
        for (int i = 0; i < 4; i++)
#pragma unroll
            for (int j = 0; j < 4; j++) s[i][j] = 0.f;

#pragma unroll
        for (int d4 = 0; d4 < 16; d4++) {
            float4 a0 = *(const float4*)&Qs[(4 * ty + 0) * 64 + d4 * 4];
            float4 a1 = *(const float4*)&Qs[(4 * ty + 1) * 64 + d4 * 4];
            float4 a2 = *(const float4*)&Qs[(4 * ty + 2) * 64 + d4 * 4];
            float4 a3 = *(const float4*)&Qs[(4 * ty + 3) * 64 + d4 * 4];
            float4 bb[4];
#pragma unroll
            for (int j = 0; j < 4; j++) {
                int kj = 4 * tx + j;
                int slot = (d4 + kj + tx) & 15;   // kj>>2 == tx for j<4
                bb[j] = *(const float4*)&KPs[kj * 64 + slot * 4];
            }
#pragma unroll
            for (int j = 0; j < 4; j++) {
                s[0][j] += a0.x * bb[j].x + a0.y * bb[j].y + a0.z * bb[j].z + a0.w * bb[j].w;
                s[1][j] += a1.x * bb[j].x + a1.y * bb[j].y + a1.z * bb[j].z + a1.w * bb[j].w;
                s[2][j] += a2.x * bb[j].x + a2.y * bb[j].y + a2.z * bb[j].z + a2.w * bb[j].w;
                s[3][j] += a3.x * bb[j].x + a3.y * bb[j].y + a3.z * bb[j].z + a3.w * bb[j].w;
            }
        }

        // ---- online softmax (row reductions across the 16 tx lanes) ----
#pragma unroll
        for (int i = 0; i < 4; i++) {
            float mt = fmaxf(fmaxf(s[i][0], s[i][1]), fmaxf(s[i][2], s[i][3]));
            mt = fmaxf(mt, __shfl_xor_sync(0xffffffffu, mt, 1));
            mt = fmaxf(mt, __shfl_xor_sync(0xffffffffu, mt, 2));
            mt = fmaxf(mt, __shfl_xor_sync(0xffffffffu, mt, 4));
            mt = fmaxf(mt, __shfl_xor_sync(0xffffffffu, mt, 8));
            float mn = fmaxf(m[i], mt);
            float alpha = __expf(m[i] - mn);
            m[i] = mn;
            float rs = 0.f;
#pragma unroll
            for (int j = 0; j < 4; j++) {
                s[i][j] = __expf(s[i][j] - mn);
                rs += s[i][j];
            }
            rs += __shfl_xor_sync(0xffffffffu, rs, 1);
            rs += __shfl_xor_sync(0xffffffffu, rs, 2);
            rs += __shfl_xor_sync(0xffffffffu, rs, 4);
            rs += __shfl_xor_sync(0xffffffffu, rs, 8);
            l[i] = l[i] * alpha + rs;
#pragma unroll
            for (int j = 0; j < 4; j++) o[i][j] *= alpha;
        }

        __syncthreads();   // everyone done reading K before P overwrites it
#pragma unroll
        for (int i = 0; i < 4; i++) {
            float4 pr; pr.x = s[i][0]; pr.y = s[i][1]; pr.z = s[i][2]; pr.w = s[i][3];
            *(float4*)&KPs[(4 * ty + i) * 64 + 4 * tx] = pr;
        }
        __syncthreads();

        // ---- O += P V ----
#pragma unroll
        for (int k4 = 0; k4 < 16; k4++) {
            float4 p0 = *(const float4*)&KPs[(4 * ty + 0) * 64 + k4 * 4];
            float4 p1 = *(const float4*)&KPs[(4 * ty + 1) * 64 + k4 * 4];
            float4 p2 = *(const float4*)&KPs[(4 * ty + 2) * 64 + k4 * 4];
            float4 p3 = *(const float4*)&KPs[(4 * ty + 3) * 64 + k4 * 4];
            float4 v0 = *(const float4*)&Vs[(k4 * 4 + 0) * 64 + 4 * tx];
            float4 v1 = *(const float4*)&Vs[(k4 * 4 + 1) * 64 + 4 * tx];
            float4 v2 = *(const float4*)&Vs[(k4 * 4 + 2) * 64 + 4 * tx];
            float4 v3 = *(const float4*)&Vs[(k4 * 4 + 3) * 64 + 4 * tx];

            o[0][0] += p0.x * v0.x + p0.y * v1.x + p0.z * v2.x + p0.w * v3.x;
            o[0][1] += p0.x * v0.y + p0.y * v1.y + p0.z * v2.y + p0.w * v3.y;
            o[0][2] += p0.x * v0.z + p0.y * v1.z + p0.z * v2.z + p0.w * v3.z;
            o[0][3] += p0.x * v0.w + p0.y * v1.w + p0.z * v2.w + p0.w * v3.w;

            o[1][0] += p1.x * v0.x + p1.y * v1.x + p1.z * v2.x + p1.w * v3.x;
            o[1][1] += p1.x * v0.y + p1.y * v1.y + p1.z * v2.y + p1.w * v3.y;
            o[1][2] += p1.x * v0.z + p1.y * v1.z + p1.z * v2.z + p1.w * v3.z;
            o[1][3] += p1.x * v0.w + p1.y * v1.w + p1.z * v2.w + p1.w * v3.w;

            o[2][0] += p2.x * v0.x + p2.y * v1.x + p2.z * v2.x + p2.w * v3.x;
            o[2][1] += p2.x * v0.y + p2.y * v1.y + p2.z * v2.y + p2.w * v3.y;
            o[2][2] += p2.x * v0.z + p2.y * v1.z + p2.z * v2.z + p2.w * v3.z;
            o[2][3] += p2.x * v0.w + p2.y * v1.w + p2.z * v2.w + p2.w * v3.w;

            o[3][0] += p3.x * v0.x + p3.y * v1.x + p3.z * v2.x + p3.w * v3.x;
            o[3][1] += p3.x * v0.y + p3.y * v1.y + p3.z * v2.y + p3.w * v3.y;
            o[3][2] += p3.x * v0.z + p3.y * v1.z + p3.z * v2.z + p3.w * v3.z;
            o[3][3] += p3.x * v0.w + p3.y * v1.w + p3.z * v2.w + p3.w * v3.w;
        }
    }

    // normalize and write to [b, s, h*64 + d]
    float* Og = g_AO + (size_t)b * SEQ * D_MODEL + h * DH;
#pragma unroll
    for (int i = 0; i < 4; i++) {
        float inv = 1.f / l[i];
        float4 r;
        r.x = o[i][0] * inv; r.y = o[i][1] * inv;
        r.z = o[i][2] * inv; r.w = o[i][3] * inv;
        *(float4*)(Og + (size_t)(qb + 4 * ty + i) * D_MODEL + 4 * tx) = r;
    }
}

// ---------------- launch ------------------------------------------------------
extern "C" void kernel_launch(void* const* d_in, const int* in_sizes, int n_in,
                              void* d_out, int out_size)
{
    (void)in_sizes; (void)n_in; (void)out_size;
    const float* query = (const float*)d_in[0];
    const float* key   = (const float*)d_in[1];
    const float* value = (const float*)d_in[2];

    // TT cores -> dense W (q,k,v,o)
    build_w_kernel<<<4096, 256>>>((const float*)d_in[3],  (const float*)d_in[4],  0);
    build_w_kernel<<<4096, 256>>>((const float*)d_in[6],  (const float*)d_in[7],  1);
    build_w_kernel<<<4096, 256>>>((const float*)d_in[9],  (const float*)d_in[10], 2);
    build_w_kernel<<<4096, 256>>>((const float*)d_in[12], (const float*)d_in[13], 3);

    dim3 gg(D_MODEL / BN, MROWS / BM);   // (8, 32)
    gemm_kernel<<<gg, 256>>>(query, 0, 0, (const float*)d_in[5],  nullptr, 0);
    gemm_kernel<<<gg, 256>>>(key,   1, 1, (const float*)d_in[8],  nullptr, 1);
    gemm_kernel<<<gg, 256>>>(value, 2, 2, (const float*)d_in[11], nullptr, 2);

    flash_kernel<<<dim3(SEQ / 64, NH, BATCH), 256>>>();

    gemm_kernel<<<gg, 256>>>(nullptr, 3, 3, (const float*)d_in[14],
                             (float*)d_out, 3);
}